// round 14
// baseline (speedup 1.0000x reference)
#include <cuda_runtime.h>
#include <cuda_fp16.h>
#include <cstdint>

#define Bc 2
#define Cc 64
#define Nn 8192
#define TQc 64
#define NCH (Nn / 64)     // 128 chunks of 64 keys

// ---------------- device scratch (fp16 splits) ----------------
__device__ __align__(256) __half g_Qhi [Bc * Nn * Cc];  // [b][n][c] (pre-scaled by log2e)
__device__ __align__(256) __half g_Qmid[Bc * Nn * Cc];
__device__ __align__(256) __half g_Khi [Bc * Nn * Cc];  // [b][n][c]
__device__ __align__(256) __half g_Kmid[Bc * Nn * Cc];
__device__ __align__(256) __half g_V   [Bc * Cc * Nn];  // [b][c][n]

// ---------------- helpers ----------------
__device__ __forceinline__ uint32_t smem_u32(const void* p) {
    uint32_t a;
    asm("{ .reg .u64 t; cvta.to.shared.u64 t, %1; cvt.u32.u64 %0, t; }" : "=r"(a) : "l"(p));
    return a;
}
__device__ __forceinline__ void cp16(void* dst, const void* src) {
    unsigned d = smem_u32(dst);
    asm volatile("cp.async.cg.shared.global [%0], [%1], 16;" :: "r"(d), "l"(src));
}
__device__ __forceinline__ void cp_commit() { asm volatile("cp.async.commit_group;" ::: "memory"); }
__device__ __forceinline__ void cp_wait0()  { asm volatile("cp.async.wait_group 0;" ::: "memory"); }
__device__ __forceinline__ void cp_wait1()  { asm volatile("cp.async.wait_group 1;" ::: "memory"); }

__device__ __forceinline__ void ldsm4(uint32_t* r, uint32_t addr) {
    asm volatile("ldmatrix.sync.aligned.m8n8.x4.shared.b16 {%0,%1,%2,%3}, [%4];"
        : "=r"(r[0]), "=r"(r[1]), "=r"(r[2]), "=r"(r[3]) : "r"(addr));
}
__device__ __forceinline__ void mma16816(float* d, const uint32_t* a, const uint32_t* b) {
    asm volatile("mma.sync.aligned.m16n8k16.row.col.f32.f16.f16.f32 "
        "{%0,%1,%2,%3}, {%4,%5,%6,%7}, {%8,%9}, {%0,%1,%2,%3};"
        : "+f"(d[0]), "+f"(d[1]), "+f"(d[2]), "+f"(d[3])
        : "r"(a[0]), "r"(a[1]), "r"(a[2]), "r"(a[3]), "r"(b[0]), "r"(b[1]));
}
__device__ __forceinline__ uint32_t cvtf2(float hi, float lo) {
    uint32_t d;
    asm("cvt.rn.f16x2.f32 %0, %1, %2;" : "=r"(d) : "f"(hi), "f"(lo));
    return d;
}
__device__ __forceinline__ uint32_t ex2h2(uint32_t x) {
    uint32_t d;
    asm("ex2.approx.f16x2 %0, %1;" : "=r"(d) : "r"(x));
    return d;
}
__device__ __forceinline__ float fex2(float x) {
    float y;
    asm("ex2.approx.f32 %0, %1;" : "=f"(y) : "f"(x));
    return y;
}
__device__ __forceinline__ float2 unpackh2(uint32_t p) {
    __half2 h = *reinterpret_cast<__half2*>(&p);
    return __half22float2(h);
}

// XOR-swizzled address within a tile of 128B rows (c16 = 16-byte column 0..7)
__device__ __forceinline__ uint32_t swz(uint32_t row, uint32_t c16) {
    return row * 128 + ((c16 ^ (row & 7)) << 4);
}

// ---------------------------------------------------------------------------
// Preproc: three 64x64 projections + BN fold; emit fp16 hi/mid splits.
// 512 threads: col = tid&127, o-quarter = tid>>7 (4 warps/SMSP for latency).
// Q is pre-scaled by log2(e) so softmax uses raw ex2.
// ---------------------------------------------------------------------------
extern "C" __global__ void __launch_bounds__(512)
preproc_kernel(const float* __restrict__ x,
               const float* __restrict__ wa, const float* __restrict__ ba,
               const float* __restrict__ wb, const float* __restrict__ bb,
               const float* __restrict__ wm, const float* __restrict__ bm,
               const float* __restrict__ gam, const float* __restrict__ bet,
               const float* __restrict__ mean, const float* __restrict__ var)
{
    extern __shared__ float sm[];
    float* swA = sm;             // 4096
    float* swB = sm + 4096;
    float* swM = sm + 8192;
    float* sBa = sm + 12288;
    float* sBb = sBa + 64;
    float* sS  = sBb + 64;
    float* sT  = sS + 64;
    float* sa  = sm + 12544;     // 128*65
    float* sb  = sa + 128 * 65;

    const int tid = threadIdx.x;
    for (int i = tid; i < 4096; i += 512) { swA[i] = wa[i]; swB[i] = wb[i]; swM[i] = wm[i]; }
    if (tid < 64) {
        sBa[tid] = ba[tid];
        sBb[tid] = bb[tid];
        float s = gam[tid] * rsqrtf(var[tid] + 1e-5f);
        sS[tid] = s;
        sT[tid] = (bm[tid] - mean[tid]) * s + bet[tid];
    }
    __syncthreads();

    const int b   = blockIdx.y;
    const int n0  = blockIdx.x * 128;
    const int col = tid & 127;
    const int oq  = tid >> 7;          // o-quarter 0..3
    const int n   = n0 + col;

    float xc[64];
    #pragma unroll
    for (int c = 0; c < 64; c++)
        xc[c] = x[((size_t)b * Cc + c) * Nn + n];

    for (int oo = 0; oo < 16; oo++) {
        const int o = 16 * oq + oo;
        float a0 = 0.f, b0 = 0.f, m0 = 0.f;
        const float4* wA4 = (const float4*)(swA + o * 64);
        const float4* wB4 = (const float4*)(swB + o * 64);
        const float4* wM4 = (const float4*)(swM + o * 64);
        #pragma unroll
        for (int c4 = 0; c4 < 16; c4++) {
            float4 va = wA4[c4], vb = wB4[c4], vm = wM4[c4];
            float x0 = xc[4*c4+0], x1 = xc[4*c4+1], x2 = xc[4*c4+2], x3 = xc[4*c4+3];
            a0 = fmaf(va.x, x0, a0); a0 = fmaf(va.y, x1, a0); a0 = fmaf(va.z, x2, a0); a0 = fmaf(va.w, x3, a0);
            b0 = fmaf(vb.x, x0, b0); b0 = fmaf(vb.y, x1, b0); b0 = fmaf(vb.z, x2, b0); b0 = fmaf(vb.w, x3, b0);
            m0 = fmaf(vm.x, x0, m0); m0 = fmaf(vm.y, x1, m0); m0 = fmaf(vm.z, x2, m0); m0 = fmaf(vm.w, x3, m0);
        }
        sa[col * 65 + o] = (a0 + sBa[o]) * 1.4426950408889634f;   // fold log2e into Q
        sb[col * 65 + o] = b0 + sBb[o];
        float v = fmaf(m0, sS[o], sT[o]);
        g_V[((size_t)b * Cc + o) * Nn + n] = __float2half(v);
    }
    __syncthreads();

    for (int e = tid; e < 128 * 64; e += 512) {
        int r = e >> 6, c = e & 63;
        size_t gi = ((size_t)b * Nn + n0 + r) * 64 + c;
        float va = sa[r * 65 + c];
        __half h = __float2half(va);
        g_Qhi[gi]  = h;
        g_Qmid[gi] = __float2half(va - __half2float(h));
        float vb = sb[r * 65 + c];
        __half h2 = __float2half(vb);
        g_Khi[gi]  = h2;
        g_Kmid[gi] = __float2half(vb - __half2float(h2));
    }
}

// ---------------------------------------------------------------------------
// Flash attention: CTA = 64 queries, 128 threads (4 warps x 16 q-rows),
// TWO CTAs per SM (grid 256, 1 wave). Co-resident CTAs have independent
// barriers -> phases drift -> each SMSP's 2 warps (from different CTAs)
// fill each other's tensor-pipe holes. Inner loop = proven 64-key chunk:
// QK fp16 3-term, vector ex2.approx.f16x2 softmax, vote-gated rescale,
// PV 1-term. smem/CTA: Q 16KB + ring-3 x 24KB = 88KB (2 CTAs = 176KB).
// ---------------------------------------------------------------------------
#define OFF_Q  0
#define OFF_KV 16384
#define CHUNK_B 24576
#define SMEM_SZ (16384 + 3 * CHUNK_B)      // 88 KB

extern "C" __global__ void __launch_bounds__(128, 2)
attn_kernel(const float* __restrict__ feat, const float* __restrict__ alphap,
            float* __restrict__ out)
{
    extern __shared__ char smc[];
    const uint32_t sb32 = smem_u32(smc);
    const int tid = threadIdx.x;
    const int w   = tid >> 5;          // 0..3
    const int l   = tid & 31;
    const int b   = blockIdx.y;
    const int n0  = blockIdx.x * TQc;

    const __half* QhiG  = g_Qhi  + (size_t)b * Nn * Cc;
    const __half* QmidG = g_Qmid + (size_t)b * Nn * Cc;
    const __half* KhiG  = g_Khi  + (size_t)b * Nn * Cc;
    const __half* KmidG = g_Kmid + (size_t)b * Nn * Cc;
    const __half* VG    = g_V    + (size_t)b * Cc * Nn;

    // ---- issue Q loads (group 0, together with chunk 0): 64 rows x 8 c16 ----
    #pragma unroll
    for (int i = 0; i < 4; i++) {
        int u = tid + i * 128;            // 0..511 (16B units)
        int row = u >> 3, c16 = u & 7;
        uint32_t d = swz(row, c16);
        cp16(smc + OFF_Q + d,        QhiG  + (size_t)(n0 + row) * 64 + c16 * 8);
        cp16(smc + OFF_Q + 8192 + d, QmidG + (size_t)(n0 + row) * 64 + c16 * 8);
    }

    auto load_chunk = [&](int jj) {
        char* base = smc + OFF_KV + (jj % 3) * CHUNK_B;
        int m0 = jj * 64;
        #pragma unroll
        for (int i = 0; i < 4; i++) {
            int u = tid + i * 128;        // 0..511
            int row = u >> 3, c16 = u & 7;
            uint32_t d = swz(row, c16);
            cp16(base + d,         KhiG  + (size_t)(m0 + row) * 64 + c16 * 8);
            cp16(base + 8192 + d,  KmidG + (size_t)(m0 + row) * 64 + c16 * 8);
            cp16(base + 16384 + d, VG + (size_t)row * Nn + m0 + c16 * 8);
        }
        cp_commit();
    };

    load_chunk(0);           // group 0: Q + chunk0
    load_chunk(1);           // group 1: chunk1
    cp_wait1();
    __syncthreads();

    // ---- Q fragments (persistent): A of m16n8k16, rows 16w..16w+15 ----
    uint32_t qh[4][4], qm[4][4];
    {
        uint32_t qrow = 16 * w + (l & 15);
        #pragma unroll
        for (int s = 0; s < 4; s++) {
            uint32_t a = sb32 + OFF_Q + swz(qrow, 2 * s + (l >> 4));
            ldsm4(qh[s], a);
            ldsm4(qm[s], a + 8192);
        }
    }

    float O[8][4];
    #pragma unroll
    for (int t = 0; t < 8; t++)
        #pragma unroll
        for (int i = 0; i < 4; i++) O[t][i] = 0.f;
    float l0 = 0.f, l1 = 0.f;
    float mr0 = -1e30f, mr1 = -1e30f;     // running row maxima (log2 units)

    const uint32_t row_b = (l & 7) + ((l >> 4) & 1) * 8;   // B-frag row within 16-tile
    const uint32_t c_b   = (l >> 3) & 1;                   // B-frag 16B-col select

    for (int j = 0; j < NCH; j++) {
        if (j >= NCH - 2) cp_wait0(); else cp_wait1();
        __syncthreads();
        const uint32_t kvb = sb32 + OFF_KV + (uint32_t)(j % 3) * CHUNK_B;

        // prefetch chunk j+2 (buffer consumed at iteration j-1; top barrier guards)
        if (j + 2 < NCH) load_chunk(j + 2);

        // ---- S = Qh*Kh + Qm*Kh + Qh*Km : term sweeps, RAW distance 8 ----
        float S[8][4];
        #pragma unroll
        for (int t = 0; t < 8; t++)
            #pragma unroll
            for (int i = 0; i < 4; i++) S[t][i] = 0.f;

        #pragma unroll
        for (int s = 0; s < 4; s++) {
            uint32_t kf[4][4];
            #pragma unroll
            for (int t = 0; t < 4; t++)
                ldsm4(kf[t], kvb + swz(16 * t + row_b, 2 * s + c_b));
            #pragma unroll
            for (int t = 0; t < 4; t++) {
                mma16816(S[2*t],   qh[s], &kf[t][0]);
                mma16816(S[2*t+1], qh[s], &kf[t][2]);
            }
            #pragma unroll
            for (int t = 0; t < 4; t++) {
                mma16816(S[2*t],   qm[s], &kf[t][0]);
                mma16816(S[2*t+1], qm[s], &kf[t][2]);
            }
            #pragma unroll
            for (int t = 0; t < 4; t++)
                ldsm4(kf[t], kvb + 8192 + swz(16 * t + row_b, 2 * s + c_b));
            #pragma unroll
            for (int t = 0; t < 4; t++) {
                mma16816(S[2*t],   qh[s], &kf[t][0]);
                mma16816(S[2*t+1], qh[s], &kf[t][2]);
            }
        }

        // ---- per-row chunk max + vote-gated running-max rescale ----
        {
            float m0 = fmaxf(S[0][0], S[0][1]);
            float m1 = fmaxf(S[0][2], S[0][3]);
            #pragma unroll
            for (int t = 1; t < 8; t++) {
                m0 = fmaxf(m0, fmaxf(S[t][0], S[t][1]));
                m1 = fmaxf(m1, fmaxf(S[t][2], S[t][3]));
            }
            m0 = fmaxf(m0, __shfl_xor_sync(0xffffffffu, m0, 1));
            m0 = fmaxf(m0, __shfl_xor_sync(0xffffffffu, m0, 2));
            m1 = fmaxf(m1, __shfl_xor_sync(0xffffffffu, m1, 1));
            m1 = fmaxf(m1, __shfl_xor_sync(0xffffffffu, m1, 2));
            bool need = (m0 > mr0) || (m1 > mr1);
            if (__any_sync(0xffffffffu, need)) {
                float M0 = fmaxf(mr0, m0), M1 = fmaxf(mr1, m1);
                float f0 = fex2(mr0 - M0), f1 = fex2(mr1 - M1);
                mr0 = M0; mr1 = M1;
                l0 *= f0; l1 *= f1;
                #pragma unroll
                for (int t = 0; t < 8; t++) {
                    O[t][0] *= f0; O[t][1] *= f0;
                    O[t][2] *= f1; O[t][3] *= f1;
                }
            }
        }

        // ---- softmax (pack f16x2, vector ex2) + 1-term PV ----
        #pragma unroll
        for (int s = 0; s < 4; s++) {
            uint32_t ah[4];
            {
                float* c0 = S[2 * s];
                float* c1 = S[2 * s + 1];
                uint32_t t0 = cvtf2(c0[1] - mr0, c0[0] - mr0);
                uint32_t t1 = cvtf2(c0[3] - mr1, c0[2] - mr1);
                uint32_t t2 = cvtf2(c1[1] - mr0, c1[0] - mr0);
                uint32_t t3 = cvtf2(c1[3] - mr1, c1[2] - mr1);
                ah[0] = ex2h2(t0);
                ah[1] = ex2h2(t1);
                ah[2] = ex2h2(t2);
                ah[3] = ex2h2(t3);
                // l from the ROUNDED P so O/l shares the rounding error
                float2 a0 = unpackh2(ah[0]), a2 = unpackh2(ah[2]);
                float2 a1 = unpackh2(ah[1]), a3 = unpackh2(ah[3]);
                l0 += a0.x + a0.y + a2.x + a2.y;
                l1 += a1.x + a1.y + a3.x + a3.y;
            }
            uint32_t vf[4][4];
            #pragma unroll
            for (int t = 0; t < 4; t++)
                ldsm4(vf[t], kvb + 16384 + swz(16 * t + row_b, 2 * s + c_b));
            #pragma unroll
            for (int t = 0; t < 4; t++) {
                mma16816(O[2*t],   ah, &vf[t][0]);
                mma16816(O[2*t+1], ah, &vf[t][2]);
            }
        }
    }

    // ---- epilogue ----
    l0 += __shfl_xor_sync(0xffffffffu, l0, 1);
    l0 += __shfl_xor_sync(0xffffffffu, l0, 2);
    l1 += __shfl_xor_sync(0xffffffffu, l1, 1);
    l1 += __shfl_xor_sync(0xffffffffu, l1, 2);
    const float ta = 2.f * alphap[0];
    const float s0 = ta / l0, s1 = ta / l1;

    __syncthreads();
    float* Ost = (float*)smc;                  // 64 x 72 staging (18.4 KB)
    {
        int r  = l >> 2, c2 = (l & 3) * 2;
        int q0 = 16 * w + r;
        #pragma unroll
        for (int t = 0; t < 8; t++) {
            int cout = 8 * t + c2;
            *(float2*)&Ost[q0 * 72 + cout]       = make_float2(O[t][0] * s0, O[t][1] * s0);
            *(float2*)&Ost[(q0 + 8) * 72 + cout] = make_float2(O[t][2] * s1, O[t][3] * s1);
        }
    }
    __syncthreads();
    {
        int cout = tid >> 1;               // 0..63
        int qb   = (tid & 1) * 32;
        const size_t rowbase = ((size_t)b * Cc + cout) * Nn + n0;
        #pragma unroll
        for (int i = 0; i < 8; i++) {
            int q = qb + 4 * i;
            float4 f = *(const float4*)&feat[rowbase + q];
            float4 o;
            o.x = fmaf(2.f, f.x, Ost[(q + 0) * 72 + cout]);
            o.y = fmaf(2.f, f.y, Ost[(q + 1) * 72 + cout]);
            o.z = fmaf(2.f, f.z, Ost[(q + 2) * 72 + cout]);
            o.w = fmaf(2.f, f.w, Ost[(q + 3) * 72 + cout]);
            *(float4*)&out[rowbase + q] = o;
        }
    }
}

// ---------------------------------------------------------------------------
extern "C" void kernel_launch(void* const* d_in, const int* in_sizes, int n_in,
                              void* d_out, int out_size)
{
    const float* feat = (const float*)d_in[0];
    const float* wa   = (const float*)d_in[1];
    const float* ba   = (const float*)d_in[2];
    const float* wb   = (const float*)d_in[3];
    const float* bb   = (const float*)d_in[4];
    const float* wm   = (const float*)d_in[5];
    const float* bm   = (const float*)d_in[6];
    const float* gam  = (const float*)d_in[7];
    const float* bet  = (const float*)d_in[8];
    const float* mean = (const float*)d_in[9];
    const float* var  = (const float*)d_in[10];
    const float* alph = (const float*)d_in[11];

    const int pre_smem = (12544 + 2 * 128 * 65) * 4;
    cudaFuncSetAttribute(preproc_kernel, cudaFuncAttributeMaxDynamicSharedMemorySize, pre_smem);
    cudaFuncSetAttribute(attn_kernel,    cudaFuncAttributeMaxDynamicSharedMemorySize, SMEM_SZ);

    preproc_kernel<<<dim3(Nn / 128, Bc), 512, pre_smem>>>(
        feat, wa, ba, wb, bb, wm, bm, gam, bet, mean, var);

    attn_kernel<<<dim3(Nn / TQc, Bc), 128, SMEM_SZ>>>(
        feat, alph, (float*)d_out);
}

// round 15
// speedup vs baseline: 1.0009x; 1.0009x over previous
#include <cuda_runtime.h>
#include <cuda_fp16.h>
#include <cstdint>

#define Bc 2
#define Cc 64
#define Nn 8192
#define TKc 128
#define NCH (Nn / TKc)    // 64 chunks of 128 keys (2 x 64-key halves)

// ---------------- device scratch (fp16 splits) ----------------
__device__ __align__(256) __half g_Qhi [Bc * Nn * Cc];  // [b][n][c] (pre-scaled by log2e)
__device__ __align__(256) __half g_Qmid[Bc * Nn * Cc];
__device__ __align__(256) __half g_Khi [Bc * Nn * Cc];  // [b][n][c]
__device__ __align__(256) __half g_Kmid[Bc * Nn * Cc];
__device__ __align__(256) __half g_V   [Bc * Cc * Nn];  // [b][c][n]

// ---------------- helpers ----------------
__device__ __forceinline__ uint32_t smem_u32(const void* p) {
    uint32_t a;
    asm("{ .reg .u64 t; cvta.to.shared.u64 t, %1; cvt.u32.u64 %0, t; }" : "=r"(a) : "l"(p));
    return a;
}
__device__ __forceinline__ void cp16(void* dst, const void* src) {
    unsigned d = smem_u32(dst);
    asm volatile("cp.async.cg.shared.global [%0], [%1], 16;" :: "r"(d), "l"(src));
}
__device__ __forceinline__ void cp_commit() { asm volatile("cp.async.commit_group;" ::: "memory"); }
__device__ __forceinline__ void cp_wait0()  { asm volatile("cp.async.wait_group 0;" ::: "memory"); }
__device__ __forceinline__ void cp_wait1()  { asm volatile("cp.async.wait_group 1;" ::: "memory"); }
__device__ __forceinline__ void cp_wait2()  { asm volatile("cp.async.wait_group 2;" ::: "memory"); }

__device__ __forceinline__ void ldsm4(uint32_t* r, uint32_t addr) {
    asm volatile("ldmatrix.sync.aligned.m8n8.x4.shared.b16 {%0,%1,%2,%3}, [%4];"
        : "=r"(r[0]), "=r"(r[1]), "=r"(r[2]), "=r"(r[3]) : "r"(addr));
}
__device__ __forceinline__ void mma16816(float* d, const uint32_t* a, const uint32_t* b) {
    asm volatile("mma.sync.aligned.m16n8k16.row.col.f32.f16.f16.f32 "
        "{%0,%1,%2,%3}, {%4,%5,%6,%7}, {%8,%9}, {%0,%1,%2,%3};"
        : "+f"(d[0]), "+f"(d[1]), "+f"(d[2]), "+f"(d[3])
        : "r"(a[0]), "r"(a[1]), "r"(a[2]), "r"(a[3]), "r"(b[0]), "r"(b[1]));
}
__device__ __forceinline__ uint32_t cvtf2(float hi, float lo) {
    uint32_t d;
    asm("cvt.rn.f16x2.f32 %0, %1, %2;" : "=r"(d) : "f"(hi), "f"(lo));
    return d;
}
__device__ __forceinline__ uint32_t ex2h2(uint32_t x) {
    uint32_t d;
    asm("ex2.approx.f16x2 %0, %1;" : "=r"(d) : "r"(x));
    return d;
}
__device__ __forceinline__ float fex2(float x) {
    float y;
    asm("ex2.approx.f32 %0, %1;" : "=f"(y) : "f"(x));
    return y;
}
__device__ __forceinline__ float2 unpackh2(uint32_t p) {
    __half2 h = *reinterpret_cast<__half2*>(&p);
    return __half22float2(h);
}

// XOR-swizzled address within a tile of 128B rows (c16 = 16-byte column 0..7)
__device__ __forceinline__ uint32_t swz(uint32_t row, uint32_t c16) {
    return row * 128 + ((c16 ^ (row & 7)) << 4);
}

// ---------------------------------------------------------------------------
// Preproc: three 64x64 projections + BN fold; emit fp16 hi/mid splits.
// 512 threads: col = tid&127, o-quarter = tid>>7 (4 warps/SMSP for latency).
// Q is pre-scaled by log2(e) so softmax uses raw ex2.
// ---------------------------------------------------------------------------
extern "C" __global__ void __launch_bounds__(512)
preproc_kernel(const float* __restrict__ x,
               const float* __restrict__ wa, const float* __restrict__ ba,
               const float* __restrict__ wb, const float* __restrict__ bb,
               const float* __restrict__ wm, const float* __restrict__ bm,
               const float* __restrict__ gam, const float* __restrict__ bet,
               const float* __restrict__ mean, const float* __restrict__ var)
{
    extern __shared__ float sm[];
    float* swA = sm;             // 4096
    float* swB = sm + 4096;
    float* swM = sm + 8192;
    float* sBa = sm + 12288;
    float* sBb = sBa + 64;
    float* sS  = sBb + 64;
    float* sT  = sS + 64;
    float* sa  = sm + 12544;     // 128*65
    float* sb  = sa + 128 * 65;

    const int tid = threadIdx.x;
    for (int i = tid; i < 4096; i += 512) { swA[i] = wa[i]; swB[i] = wb[i]; swM[i] = wm[i]; }
    if (tid < 64) {
        sBa[tid] = ba[tid];
        sBb[tid] = bb[tid];
        float s = gam[tid] * rsqrtf(var[tid] + 1e-5f);
        sS[tid] = s;
        sT[tid] = (bm[tid] - mean[tid]) * s + bet[tid];
    }
    __syncthreads();

    const int b   = blockIdx.y;
    const int n0  = blockIdx.x * 128;
    const int col = tid & 127;
    const int oq  = tid >> 7;          // o-quarter 0..3
    const int n   = n0 + col;

    float xc[64];
    #pragma unroll
    for (int c = 0; c < 64; c++)
        xc[c] = x[((size_t)b * Cc + c) * Nn + n];

    for (int oo = 0; oo < 16; oo++) {
        const int o = 16 * oq + oo;
        float a0 = 0.f, b0 = 0.f, m0 = 0.f;
        const float4* wA4 = (const float4*)(swA + o * 64);
        const float4* wB4 = (const float4*)(swB + o * 64);
        const float4* wM4 = (const float4*)(swM + o * 64);
        #pragma unroll
        for (int c4 = 0; c4 < 16; c4++) {
            float4 va = wA4[c4], vb = wB4[c4], vm = wM4[c4];
            float x0 = xc[4*c4+0], x1 = xc[4*c4+1], x2 = xc[4*c4+2], x3 = xc[4*c4+3];
            a0 = fmaf(va.x, x0, a0); a0 = fmaf(va.y, x1, a0); a0 = fmaf(va.z, x2, a0); a0 = fmaf(va.w, x3, a0);
            b0 = fmaf(vb.x, x0, b0); b0 = fmaf(vb.y, x1, b0); b0 = fmaf(vb.z, x2, b0); b0 = fmaf(vb.w, x3, b0);
            m0 = fmaf(vm.x, x0, m0); m0 = fmaf(vm.y, x1, m0); m0 = fmaf(vm.z, x2, m0); m0 = fmaf(vm.w, x3, m0);
        }
        sa[col * 65 + o] = (a0 + sBa[o]) * 1.4426950408889634f;   // fold log2e into Q
        sb[col * 65 + o] = b0 + sBb[o];
        float v = fmaf(m0, sS[o], sT[o]);
        g_V[((size_t)b * Cc + o) * Nn + n] = __float2half(v);
    }
    __syncthreads();

    for (int e = tid; e < 128 * 64; e += 512) {
        int r = e >> 6, c = e & 63;
        size_t gi = ((size_t)b * Nn + n0 + r) * 64 + c;
        float va = sa[r * 65 + c];
        __half h = __float2half(va);
        g_Qhi[gi]  = h;
        g_Qmid[gi] = __float2half(va - __half2float(h));
        float vb = sb[r * 65 + c];
        __half h2 = __float2half(vb);
        g_Khi[gi]  = h2;
        g_Kmid[gi] = __float2half(vb - __half2float(h2));
    }
}

// ---------------------------------------------------------------------------
// Flash attention: CTA = 128 queries, 256 threads (8 warps x 16 q-rows).
// 128-key chunks processed as two 64-key halves in a SOFTWARE PIPELINE:
// QK MMAs of one half interleave with softmax+PV scalars of the other half
// (SA/SB accumulator sets = same register budget as the R13 16-tile S).
// K ring-3 x 32KB; V ring-4 x 16KB (PV of half B outlives chunk boundary).
// ---------------------------------------------------------------------------
#define OFF_Q  0
#define OFF_K  32768
#define OFF_V  (32768 + 3 * 32768)
#define SMEM_SZ (OFF_V + 4 * 16384)       // 192 KB

extern "C" __global__ void __launch_bounds__(256, 1)
attn_kernel(const float* __restrict__ feat, const float* __restrict__ alphap,
            float* __restrict__ out)
{
    extern __shared__ char smc[];
    const uint32_t sb32 = smem_u32(smc);
    const int tid = threadIdx.x;
    const int w   = tid >> 5;
    const int l   = tid & 31;
    const int b   = blockIdx.y;
    const int n0  = blockIdx.x * 128;

    const __half* QhiG  = g_Qhi  + (size_t)b * Nn * Cc;
    const __half* QmidG = g_Qmid + (size_t)b * Nn * Cc;
    const __half* KhiG  = g_Khi  + (size_t)b * Nn * Cc;
    const __half* KmidG = g_Kmid + (size_t)b * Nn * Cc;
    const __half* VG    = g_V    + (size_t)b * Cc * Nn;

    // ---- issue Q loads (grouped with chunk 0) ----
    #pragma unroll
    for (int i = 0; i < 4; i++) {
        int u = tid + i * 256;            // 0..1023 (16B units)
        int row = u >> 3, c16 = u & 7;
        uint32_t d = swz(row, c16);
        cp16(smc + OFF_Q + d,         QhiG  + (size_t)(n0 + row) * 64 + c16 * 8);
        cp16(smc + OFF_Q + 16384 + d, QmidG + (size_t)(n0 + row) * 64 + c16 * 8);
    }

    auto load_chunk = [&](int jj) {
        char* kb = smc + OFF_K + (jj % 3) * 32768;
        char* vb = smc + OFF_V + (jj & 3) * 16384;
        int m0 = jj * TKc;
        #pragma unroll
        for (int i = 0; i < 4; i++) {
            int u = tid + i * 256;        // 0..1023 (K: 128 rows x 8 c16)
            int row = u >> 3, c16 = u & 7;
            uint32_t d = swz(row, c16);
            cp16(kb + d,         KhiG  + (size_t)(m0 + row) * 64 + c16 * 8);
            cp16(kb + 16384 + d, KmidG + (size_t)(m0 + row) * 64 + c16 * 8);
        }
        #pragma unroll
        for (int i = 0; i < 4; i++) {
            int u = tid + i * 256;        // V: 2 subtiles x (64 ch-rows x 8 c16)
            int sub = u >> 9, r = (u >> 3) & 63, c16 = u & 7;
            cp16(vb + sub * 8192 + swz(r, c16),
                 VG + (size_t)r * Nn + m0 + sub * 64 + c16 * 8);
        }
        cp_commit();
    };

    load_chunk(0);           // group 0: Q + chunk0
    load_chunk(1);           // group 1
    load_chunk(2);           // group 2
    cp_wait2();              // Q + chunk0 landed
    __syncthreads();

    // ---- Q fragments (persistent): A of m16n8k16, rows 16w..16w+15 ----
    uint32_t qh[4][4], qm[4][4];
    {
        uint32_t qrow = 16 * w + (l & 15);
        #pragma unroll
        for (int s = 0; s < 4; s++) {
            uint32_t a = sb32 + OFF_Q + swz(qrow, 2 * s + (l >> 4));
            ldsm4(qh[s], a);
            ldsm4(qm[s], a + 16384);
        }
    }

    float O[8][4];
    #pragma unroll
    for (int t = 0; t < 8; t++)
        #pragma unroll
        for (int i = 0; i < 4; i++) O[t][i] = 0.f;
    float l0 = 0.f, l1 = 0.f;
    float mr0 = -1e30f, mr1 = -1e30f;     // running row maxima (log2 units)

    const uint32_t row_b = (l & 7) + ((l >> 4) & 1) * 8;   // B-frag row within 16-tile
    const uint32_t c_b   = (l >> 3) & 1;                   // B-frag 16B-col select

    float SA[8][4], SB[8][4];

    // QK s-step for one 64-key half into S (keys 64*hk + 16t)
    auto qk_step = [&](uint32_t kvK, int hk, float (&Sq)[8][4], int s) {
        uint32_t kf[4][4];
        #pragma unroll
        for (int t = 0; t < 4; t++)
            ldsm4(kf[t], kvK + swz(64 * hk + 16 * t + row_b, 2 * s + c_b));
        #pragma unroll
        for (int t = 0; t < 4; t++) {
            mma16816(Sq[2*t],   qh[s], &kf[t][0]);
            mma16816(Sq[2*t+1], qh[s], &kf[t][2]);
        }
        #pragma unroll
        for (int t = 0; t < 4; t++) {
            mma16816(Sq[2*t],   qm[s], &kf[t][0]);
            mma16816(Sq[2*t+1], qm[s], &kf[t][2]);
        }
        #pragma unroll
        for (int t = 0; t < 4; t++)
            ldsm4(kf[t], kvK + 16384 + swz(64 * hk + 16 * t + row_b, 2 * s + c_b));
        #pragma unroll
        for (int t = 0; t < 4; t++) {
            mma16816(Sq[2*t],   qh[s], &kf[t][0]);
            mma16816(Sq[2*t+1], qh[s], &kf[t][2]);
        }
    };

    // softmax + PV s-step for one half (vb2 = V subtile base of that half)
    auto smpv_step = [&](uint32_t vb2, float (&Sp)[8][4], int s) {
        uint32_t ah[4];
        {
            float* c0 = Sp[2 * s];
            float* c1 = Sp[2 * s + 1];
            uint32_t t0 = cvtf2(c0[1] - mr0, c0[0] - mr0);
            uint32_t t1 = cvtf2(c0[3] - mr1, c0[2] - mr1);
            uint32_t t2 = cvtf2(c1[1] - mr0, c1[0] - mr0);
            uint32_t t3 = cvtf2(c1[3] - mr1, c1[2] - mr1);
            ah[0] = ex2h2(t0);
            ah[1] = ex2h2(t1);
            ah[2] = ex2h2(t2);
            ah[3] = ex2h2(t3);
            // l from the ROUNDED P so O/l shares the rounding error
            float2 a0 = unpackh2(ah[0]), a2 = unpackh2(ah[2]);
            float2 a1 = unpackh2(ah[1]), a3 = unpackh2(ah[3]);
            l0 += a0.x + a0.y + a2.x + a2.y;
            l1 += a1.x + a1.y + a3.x + a3.y;
        }
        uint32_t vf[4][4];
        #pragma unroll
        for (int t = 0; t < 4; t++)
            ldsm4(vf[t], vb2 + swz(16 * t + row_b, 2 * s + c_b));
        #pragma unroll
        for (int t = 0; t < 4; t++) {
            mma16816(O[2*t],   ah, &vf[t][0]);
            mma16816(O[2*t+1], ah, &vf[t][2]);
        }
    };

    // max-update for one half + vote-gated rescale
    auto maxupd = [&](float (&Sq)[8][4]) {
        float m0 = fmaxf(Sq[0][0], Sq[0][1]);
        float m1 = fmaxf(Sq[0][2], Sq[0][3]);
        #pragma unroll
        for (int t = 1; t < 8; t++) {
            m0 = fmaxf(m0, fmaxf(Sq[t][0], Sq[t][1]));
            m1 = fmaxf(m1, fmaxf(Sq[t][2], Sq[t][3]));
        }
        m0 = fmaxf(m0, __shfl_xor_sync(0xffffffffu, m0, 1));
        m0 = fmaxf(m0, __shfl_xor_sync(0xffffffffu, m0, 2));
        m1 = fmaxf(m1, __shfl_xor_sync(0xffffffffu, m1, 1));
        m1 = fmaxf(m1, __shfl_xor_sync(0xffffffffu, m1, 2));
        bool need = (m0 > mr0) || (m1 > mr1);
        if (__any_sync(0xffffffffu, need)) {
            float M0 = fmaxf(mr0, m0), M1 = fmaxf(mr1, m1);
            float f0 = fex2(mr0 - M0), f1 = fex2(mr1 - M1);
            mr0 = M0; mr1 = M1;
            l0 *= f0; l1 *= f1;
            #pragma unroll
            for (int t = 0; t < 8; t++) {
                O[t][0] *= f0; O[t][1] *= f0;
                O[t][2] *= f1; O[t][3] *= f1;
            }
        }
    };

    #pragma unroll
    for (int t = 0; t < 8; t++)
        #pragma unroll
        for (int i = 0; i < 4; i++) { SA[t][i] = 0.f; SB[t][i] = 0.f; }

    // ---- prologue: QK_A(0) (not overlapped) ----
    {
        const uint32_t kvK = sb32 + OFF_K;       // chunk 0, K slot 0
        #pragma unroll
        for (int s = 0; s < 4; s++) qk_step(kvK, 0, SA, s);
        maxupd(SA);
    }

    for (int j = 0; j < NCH; j++) {
        const uint32_t kvK  = sb32 + OFF_K + (uint32_t)(j % 3) * 32768;
        const uint32_t vbj  = sb32 + OFF_V + (uint32_t)(j & 3) * 16384;

        // ---- phase beta: QK_B(j) <-> softmax+PV_A(j) ----
        #pragma unroll
        for (int s = 0; s < 4; s++) {
            qk_step(kvK, 1, SB, s);
            smpv_step(vbj, SA, s);           // V subtile 0 (keys 64j..64j+63)
        }
        maxupd(SB);
        #pragma unroll
        for (int t = 0; t < 8; t++)
            #pragma unroll
            for (int i = 0; i < 4; i++) SA[t][i] = 0.f;

        // ---- chunk boundary: make chunk j+1 resident; prefetch j+3 ----
        const bool hasNext = (j + 1 < NCH);
        if (hasNext) {
            if (j + 2 < NCH) cp_wait1(); else cp_wait0();
            __syncthreads();
            if (j + 3 < NCH) load_chunk(j + 3);
        }

        // ---- phase alpha: QK_A(j+1) <-> softmax+PV_B(j) ----
        const uint32_t kvKn = sb32 + OFF_K + (uint32_t)((j + 1) % 3) * 32768;
        #pragma unroll
        for (int s = 0; s < 4; s++) {
            if (hasNext) qk_step(kvKn, 0, SA, s);
            smpv_step(vbj + 8192, SB, s);    // V subtile 1 (keys 64j+64..+127)
        }
        if (hasNext) maxupd(SA);
        #pragma unroll
        for (int t = 0; t < 8; t++)
            #pragma unroll
            for (int i = 0; i < 4; i++) SB[t][i] = 0.f;
    }

    // ---- epilogue ----
    l0 += __shfl_xor_sync(0xffffffffu, l0, 1);
    l0 += __shfl_xor_sync(0xffffffffu, l0, 2);
    l1 += __shfl_xor_sync(0xffffffffu, l1, 1);
    l1 += __shfl_xor_sync(0xffffffffu, l1, 2);
    const float ta = 2.f * alphap[0];
    const float s0 = ta / l0, s1 = ta / l1;

    __syncthreads();
    float* Ost = (float*)smc;                  // 128 x 72 staging (36.8 KB)
    {
        int r  = l >> 2, c2 = (l & 3) * 2;
        int q0 = 16 * w + r;
        #pragma unroll
        for (int t = 0; t < 8; t++) {
            int cout = 8 * t + c2;
            *(float2*)&Ost[q0 * 72 + cout]       = make_float2(O[t][0] * s0, O[t][1] * s0);
            *(float2*)&Ost[(q0 + 8) * 72 + cout] = make_float2(O[t][2] * s1, O[t][3] * s1);
        }
    }
    __syncthreads();
    {
        int cout = tid >> 2;
        int qb   = (tid & 3) * 32;
        const size_t rowbase = ((size_t)b * Cc + cout) * Nn + n0;
        #pragma unroll
        for (int i = 0; i < 8; i++) {
            int q = qb + 4 * i;
            float4 f = *(const float4*)&feat[rowbase + q];
            float4 o;
            o.x = fmaf(2.f, f.x, Ost[(q + 0) * 72 + cout]);
            o.y = fmaf(2.f, f.y, Ost[(q + 1) * 72 + cout]);
            o.z = fmaf(2.f, f.z, Ost[(q + 2) * 72 + cout]);
            o.w = fmaf(2.f, f.w, Ost[(q + 3) * 72 + cout]);
            *(float4*)&out[rowbase + q] = o;
        }
    }
}

// ---------------------------------------------------------------------------
extern "C" void kernel_launch(void* const* d_in, const int* in_sizes, int n_in,
                              void* d_out, int out_size)
{
    const float* feat = (const float*)d_in[0];
    const float* wa   = (const float*)d_in[1];
    const float* ba   = (const float*)d_in[2];
    const float* wb   = (const float*)d_in[3];
    const float* bb   = (const float*)d_in[4];
    const float* wm   = (const float*)d_in[5];
    const float* bm   = (const float*)d_in[6];
    const float* gam  = (const float*)d_in[7];
    const float* bet  = (const float*)d_in[8];
    const float* mean = (const float*)d_in[9];
    const float* var  = (const float*)d_in[10];
    const float* alph = (const float*)d_in[11];

    const int pre_smem = (12544 + 2 * 128 * 65) * 4;
    cudaFuncSetAttribute(preproc_kernel, cudaFuncAttributeMaxDynamicSharedMemorySize, pre_smem);
    cudaFuncSetAttribute(attn_kernel,    cudaFuncAttributeMaxDynamicSharedMemorySize, SMEM_SZ);

    preproc_kernel<<<dim3(Nn / 128, Bc), 512, pre_smem>>>(
        feat, wa, ba, wb, bb, wm, bm, gam, bet, mean, var);

    attn_kernel<<<dim3(Nn / 128, Bc), 256, SMEM_SZ>>>(
        feat, alph, (float*)d_out);
}

// round 16
// speedup vs baseline: 1.2692x; 1.2681x over previous
#include <cuda_runtime.h>
#include <cuda_fp16.h>
#include <cstdint>

#define Bc 2
#define Cc 64
#define Nn 8192
#define TKc 128
#define NCH (Nn / TKc)    // 64 chunks of 128 keys

// ---------------- device scratch (fp16 splits) ----------------
__device__ __align__(256) __half g_Qhi [Bc * Nn * Cc];  // [b][n][c] (pre-scaled by log2e)
__device__ __align__(256) __half g_Qmid[Bc * Nn * Cc];
__device__ __align__(256) __half g_Khi [Bc * Nn * Cc];  // [b][n][c] (single fp16 rounding)
__device__ __align__(256) __half g_V   [Bc * Cc * Nn];  // [b][c][n]

// ---------------- helpers ----------------
__device__ __forceinline__ uint32_t smem_u32(const void* p) {
    uint32_t a;
    asm("{ .reg .u64 t; cvta.to.shared.u64 t, %1; cvt.u32.u64 %0, t; }" : "=r"(a) : "l"(p));
    return a;
}
__device__ __forceinline__ void cp16(void* dst, const void* src) {
    unsigned d = smem_u32(dst);
    asm volatile("cp.async.cg.shared.global [%0], [%1], 16;" :: "r"(d), "l"(src));
}
__device__ __forceinline__ void cp_commit() { asm volatile("cp.async.commit_group;" ::: "memory"); }
__device__ __forceinline__ void cp_wait0()  { asm volatile("cp.async.wait_group 0;" ::: "memory"); }
__device__ __forceinline__ void cp_wait1()  { asm volatile("cp.async.wait_group 1;" ::: "memory"); }

__device__ __forceinline__ void ldsm4(uint32_t* r, uint32_t addr) {
    asm volatile("ldmatrix.sync.aligned.m8n8.x4.shared.b16 {%0,%1,%2,%3}, [%4];"
        : "=r"(r[0]), "=r"(r[1]), "=r"(r[2]), "=r"(r[3]) : "r"(addr));
}
__device__ __forceinline__ void mma16816(float* d, const uint32_t* a, const uint32_t* b) {
    asm volatile("mma.sync.aligned.m16n8k16.row.col.f32.f16.f16.f32 "
        "{%0,%1,%2,%3}, {%4,%5,%6,%7}, {%8,%9}, {%0,%1,%2,%3};"
        : "+f"(d[0]), "+f"(d[1]), "+f"(d[2]), "+f"(d[3])
        : "r"(a[0]), "r"(a[1]), "r"(a[2]), "r"(a[3]), "r"(b[0]), "r"(b[1]));
}
__device__ __forceinline__ uint32_t cvtf2(float hi, float lo) {
    uint32_t d;
    asm("cvt.rn.f16x2.f32 %0, %1, %2;" : "=r"(d) : "f"(hi), "f"(lo));
    return d;
}
__device__ __forceinline__ uint32_t ex2h2(uint32_t x) {
    uint32_t d;
    asm("ex2.approx.f16x2 %0, %1;" : "=r"(d) : "r"(x));
    return d;
}
__device__ __forceinline__ float fex2(float x) {
    float y;
    asm("ex2.approx.f32 %0, %1;" : "=f"(y) : "f"(x));
    return y;
}
__device__ __forceinline__ float2 unpackh2(uint32_t p) {
    __half2 h = *reinterpret_cast<__half2*>(&p);
    return __half22float2(h);
}

// XOR-swizzled address within a tile of 128B rows (c16 = 16-byte column 0..7)
__device__ __forceinline__ uint32_t swz(uint32_t row, uint32_t c16) {
    return row * 128 + ((c16 ^ (row & 7)) << 4);
}

// ---------------------------------------------------------------------------
// Preproc: three 64x64 projections + BN fold; emit fp16 Q hi/mid + K + V.
// 512 threads: col = tid&127, o-quarter = tid>>7 (4 warps/SMSP for latency).
// Q is pre-scaled by log2(e) so softmax uses raw ex2.
// ---------------------------------------------------------------------------
extern "C" __global__ void __launch_bounds__(512)
preproc_kernel(const float* __restrict__ x,
               const float* __restrict__ wa, const float* __restrict__ ba,
               const float* __restrict__ wb, const float* __restrict__ bb,
               const float* __restrict__ wm, const float* __restrict__ bm,
               const float* __restrict__ gam, const float* __restrict__ bet,
               const float* __restrict__ mean, const float* __restrict__ var)
{
    extern __shared__ float sm[];
    float* swA = sm;             // 4096
    float* swB = sm + 4096;
    float* swM = sm + 8192;
    float* sBa = sm + 12288;
    float* sBb = sBa + 64;
    float* sS  = sBb + 64;
    float* sT  = sS + 64;
    float* sa  = sm + 12544;     // 128*65
    float* sb  = sa + 128 * 65;

    const int tid = threadIdx.x;
    for (int i = tid; i < 4096; i += 512) { swA[i] = wa[i]; swB[i] = wb[i]; swM[i] = wm[i]; }
    if (tid < 64) {
        sBa[tid] = ba[tid];
        sBb[tid] = bb[tid];
        float s = gam[tid] * rsqrtf(var[tid] + 1e-5f);
        sS[tid] = s;
        sT[tid] = (bm[tid] - mean[tid]) * s + bet[tid];
    }
    __syncthreads();

    const int b   = blockIdx.y;
    const int n0  = blockIdx.x * 128;
    const int col = tid & 127;
    const int oq  = tid >> 7;          // o-quarter 0..3
    const int n   = n0 + col;

    float xc[64];
    #pragma unroll
    for (int c = 0; c < 64; c++)
        xc[c] = x[((size_t)b * Cc + c) * Nn + n];

    for (int oo = 0; oo < 16; oo++) {
        const int o = 16 * oq + oo;
        float a0 = 0.f, b0 = 0.f, m0 = 0.f;
        const float4* wA4 = (const float4*)(swA + o * 64);
        const float4* wB4 = (const float4*)(swB + o * 64);
        const float4* wM4 = (const float4*)(swM + o * 64);
        #pragma unroll
        for (int c4 = 0; c4 < 16; c4++) {
            float4 va = wA4[c4], vb = wB4[c4], vm = wM4[c4];
            float x0 = xc[4*c4+0], x1 = xc[4*c4+1], x2 = xc[4*c4+2], x3 = xc[4*c4+3];
            a0 = fmaf(va.x, x0, a0); a0 = fmaf(va.y, x1, a0); a0 = fmaf(va.z, x2, a0); a0 = fmaf(va.w, x3, a0);
            b0 = fmaf(vb.x, x0, b0); b0 = fmaf(vb.y, x1, b0); b0 = fmaf(vb.z, x2, b0); b0 = fmaf(vb.w, x3, b0);
            m0 = fmaf(vm.x, x0, m0); m0 = fmaf(vm.y, x1, m0); m0 = fmaf(vm.z, x2, m0); m0 = fmaf(vm.w, x3, m0);
        }
        sa[col * 65 + o] = (a0 + sBa[o]) * 1.4426950408889634f;   // fold log2e into Q
        sb[col * 65 + o] = b0 + sBb[o];
        float v = fmaf(m0, sS[o], sT[o]);
        g_V[((size_t)b * Cc + o) * Nn + n] = __float2half(v);
    }
    __syncthreads();

    for (int e = tid; e < 128 * 64; e += 512) {
        int r = e >> 6, c = e & 63;
        size_t gi = ((size_t)b * Nn + n0 + r) * 64 + c;
        float va = sa[r * 65 + c];
        __half h = __float2half(va);
        g_Qhi[gi]  = h;
        g_Qmid[gi] = __float2half(va - __half2float(h));
        g_Khi[gi]  = __float2half(sb[r * 65 + c]);
    }
}

// ---------------------------------------------------------------------------
// Flash attention: CTA = 128 queries, 256 threads (8 warps x 16 q-rows).
// 128-key chunks. QK fp16 2-TERM: (Qh + Qm) * Kh — only K's single fp16
// rounding remains as QK error (cancels substantially in O/l).
// S preloaded with -mr so the softmax needs NO subtraction; range check is
// local-fmax + warp vote (shfl reduce + rescale only on rare max updates).
// smem: Q 32KB; ring-3 x 32KB chunks (Khi 16KB | V 2x8KB subtiles).
// ---------------------------------------------------------------------------
#define OFF_Q  0
#define OFF_KV 32768
#define CHUNK_B 32768
#define SMEM_SZ (32768 + 3 * CHUNK_B)      // 128 KB

extern "C" __global__ void __launch_bounds__(256, 1)
attn_kernel(const float* __restrict__ feat, const float* __restrict__ alphap,
            float* __restrict__ out)
{
    extern __shared__ char smc[];
    const uint32_t sb32 = smem_u32(smc);
    const int tid = threadIdx.x;
    const int w   = tid >> 5;
    const int l   = tid & 31;
    const int b   = blockIdx.y;
    const int n0  = blockIdx.x * 128;

    const __half* QhiG  = g_Qhi  + (size_t)b * Nn * Cc;
    const __half* QmidG = g_Qmid + (size_t)b * Nn * Cc;
    const __half* KhiG  = g_Khi  + (size_t)b * Nn * Cc;
    const __half* VG    = g_V    + (size_t)b * Cc * Nn;

    // ---- issue Q loads (group 0, together with chunk 0) ----
    #pragma unroll
    for (int i = 0; i < 4; i++) {
        int u = tid + i * 256;            // 0..1023 (16B units)
        int row = u >> 3, c16 = u & 7;
        uint32_t d = swz(row, c16);
        cp16(smc + OFF_Q + d,         QhiG  + (size_t)(n0 + row) * 64 + c16 * 8);
        cp16(smc + OFF_Q + 16384 + d, QmidG + (size_t)(n0 + row) * 64 + c16 * 8);
    }

    auto load_chunk = [&](int jj) {
        char* base = smc + OFF_KV + (jj % 3) * CHUNK_B;
        int m0 = jj * TKc;
        #pragma unroll
        for (int i = 0; i < 4; i++) {
            int u = tid + i * 256;        // K: 128 rows x 8 c16 = 1024 units
            int row = u >> 3, c16 = u & 7;
            cp16(base + swz(row, c16), KhiG + (size_t)(m0 + row) * 64 + c16 * 8);
        }
        #pragma unroll
        for (int i = 0; i < 4; i++) {
            int u = tid + i * 256;        // V: 2 subtiles x (64 ch-rows x 8 c16)
            int sub = u >> 9, r = (u >> 3) & 63, c16 = u & 7;
            cp16(base + 16384 + sub * 8192 + swz(r, c16),
                 VG + (size_t)r * Nn + m0 + sub * 64 + c16 * 8);
        }
        cp_commit();
    };

    load_chunk(0);           // group 0: Q + chunk0
    load_chunk(1);           // group 1: chunk1
    cp_wait1();
    __syncthreads();

    // ---- Q fragments (persistent): A of m16n8k16, rows 16w..16w+15 ----
    uint32_t qh[4][4], qm[4][4];
    {
        uint32_t qrow = 16 * w + (l & 15);
        #pragma unroll
        for (int s = 0; s < 4; s++) {
            uint32_t a = sb32 + OFF_Q + swz(qrow, 2 * s + (l >> 4));
            ldsm4(qh[s], a);
            ldsm4(qm[s], a + 16384);
        }
    }

    float O[8][4];
    #pragma unroll
    for (int t = 0; t < 8; t++)
        #pragma unroll
        for (int i = 0; i < 4; i++) O[t][i] = 0.f;
    float l0 = 0.f, l1 = 0.f;
    float mr0 = 0.f, mr1 = 0.f;   // softmax reference (running max, log2 units)

    const uint32_t row_b = (l & 7) + ((l >> 4) & 1) * 8;   // B-frag row within 16-tile
    const uint32_t c_b   = (l >> 3) & 1;                   // B-frag 16B-col select

    for (int j = 0; j < NCH; j++) {
        if (j >= NCH - 2) cp_wait0(); else cp_wait1();
        __syncthreads();
        const uint32_t kvb = sb32 + OFF_KV + (uint32_t)(j % 3) * CHUNK_B;

        // prefetch chunk j+2 (buffer consumed at iteration j-1; top barrier guards)
        if (j + 2 < NCH) load_chunk(j + 2);

        // ---- S = (Qh + Qm) * Kh, preloaded with -mr (softmax needs no sub) ----
        float S[16][4];
        #pragma unroll
        for (int t = 0; t < 16; t++) {
            S[t][0] = -mr0; S[t][1] = -mr0;
            S[t][2] = -mr1; S[t][3] = -mr1;
        }

        #pragma unroll
        for (int s = 0; s < 4; s++) {
            #pragma unroll
            for (int h = 0; h < 2; h++) {       // K-row halves (4 tiles each)
                uint32_t kf[4][4];
                #pragma unroll
                for (int t = 0; t < 4; t++)
                    ldsm4(kf[t], kvb + swz(16 * (4 * h + t) + row_b, 2 * s + c_b));
                #pragma unroll
                for (int t = 0; t < 4; t++) {
                    mma16816(S[8*h + 2*t],     qh[s], &kf[t][0]);
                    mma16816(S[8*h + 2*t + 1], qh[s], &kf[t][2]);
                }
                #pragma unroll
                for (int t = 0; t < 4; t++) {
                    mma16816(S[8*h + 2*t],     qm[s], &kf[t][0]);
                    mma16816(S[8*h + 2*t + 1], qm[s], &kf[t][2]);
                }
            }
        }

        // ---- range check: any S > 0 means new row max -> rare update path ----
        {
            float lm = S[0][0];
            #pragma unroll
            for (int t = 0; t < 16; t++)
                lm = fmaxf(lm, fmaxf(fmaxf(S[t][0], S[t][1]), fmaxf(S[t][2], S[t][3])));
            if (__any_sync(0xffffffffu, lm > 0.f)) {
                float m0 = -1e30f, m1 = -1e30f;
                #pragma unroll
                for (int t = 0; t < 16; t++) {
                    m0 = fmaxf(m0, fmaxf(S[t][0], S[t][1]));
                    m1 = fmaxf(m1, fmaxf(S[t][2], S[t][3]));
                }
                m0 = fmaxf(m0, __shfl_xor_sync(0xffffffffu, m0, 1));
                m0 = fmaxf(m0, __shfl_xor_sync(0xffffffffu, m0, 2));
                m1 = fmaxf(m1, __shfl_xor_sync(0xffffffffu, m1, 1));
                m1 = fmaxf(m1, __shfl_xor_sync(0xffffffffu, m1, 2));
                float d0 = fmaxf(m0, 0.f), d1 = fmaxf(m1, 0.f);
                mr0 += d0; mr1 += d1;
                float f0 = fex2(-d0), f1 = fex2(-d1);
                l0 *= f0; l1 *= f1;
                #pragma unroll
                for (int t = 0; t < 8; t++) {
                    O[t][0] *= f0; O[t][1] *= f0;
                    O[t][2] *= f1; O[t][3] *= f1;
                }
                #pragma unroll
                for (int t = 0; t < 16; t++) {
                    S[t][0] -= d0; S[t][1] -= d0;
                    S[t][2] -= d1; S[t][3] -= d1;
                }
            }
        }

        // ---- softmax (pack f16x2, vector ex2; no subtraction) + 1-term PV ----
        #pragma unroll
        for (int sg = 0; sg < 8; sg++) {
            uint32_t ah[4];
            {
                float* c0 = S[2 * sg];
                float* c1 = S[2 * sg + 1];
                uint32_t t0 = cvtf2(c0[1], c0[0]);
                uint32_t t1 = cvtf2(c0[3], c0[2]);
                uint32_t t2 = cvtf2(c1[1], c1[0]);
                uint32_t t3 = cvtf2(c1[3], c1[2]);
                ah[0] = ex2h2(t0);
                ah[1] = ex2h2(t1);
                ah[2] = ex2h2(t2);
                ah[3] = ex2h2(t3);
                // l from the ROUNDED P so O/l shares the rounding error
                float2 a0 = unpackh2(ah[0]), a2 = unpackh2(ah[2]);
                float2 a1 = unpackh2(ah[1]), a3 = unpackh2(ah[3]);
                l0 += a0.x + a0.y + a2.x + a2.y;
                l1 += a1.x + a1.y + a3.x + a3.y;
            }
            const uint32_t vb2 = kvb + 16384 + (uint32_t)(sg >> 2) * 8192;
            const uint32_t sl  = (uint32_t)(sg & 3);
            uint32_t vf[4][4];
            #pragma unroll
            for (int t = 0; t < 4; t++)
                ldsm4(vf[t], vb2 + swz(16 * t + row_b, 2 * sl + c_b));
            #pragma unroll
            for (int t = 0; t < 4; t++) {
                mma16816(O[2*t],   ah, &vf[t][0]);
                mma16816(O[2*t+1], ah, &vf[t][2]);
            }
        }
    }

    // ---- epilogue ----
    l0 += __shfl_xor_sync(0xffffffffu, l0, 1);
    l0 += __shfl_xor_sync(0xffffffffu, l0, 2);
    l1 += __shfl_xor_sync(0xffffffffu, l1, 1);
    l1 += __shfl_xor_sync(0xffffffffu, l1, 2);
    const float ta = 2.f * alphap[0];
    const float s0 = ta / l0, s1 = ta / l1;

    __syncthreads();
    float* Ost = (float*)smc;                  // 128 x 72 staging (36.8 KB)
    {
        int r  = l >> 2, c2 = (l & 3) * 2;
        int q0 = 16 * w + r;
        #pragma unroll
        for (int t = 0; t < 8; t++) {
            int cout = 8 * t + c2;
            *(float2*)&Ost[q0 * 72 + cout]       = make_float2(O[t][0] * s0, O[t][1] * s0);
            *(float2*)&Ost[(q0 + 8) * 72 + cout] = make_float2(O[t][2] * s1, O[t][3] * s1);
        }
    }
    __syncthreads();
    {
        int cout = tid >> 2;
        int qb   = (tid & 3) * 32;
        const size_t rowbase = ((size_t)b * Cc + cout) * Nn + n0;
        #pragma unroll
        for (int i = 0; i < 8; i++) {
            int q = qb + 4 * i;
            float4 f = *(const float4*)&feat[rowbase + q];
            float4 o;
            o.x = fmaf(2.f, f.x, Ost[(q + 0) * 72 + cout]);
            o.y = fmaf(2.f, f.y, Ost[(q + 1) * 72 + cout]);
            o.z = fmaf(2.f, f.z, Ost[(q + 2) * 72 + cout]);
            o.w = fmaf(2.f, f.w, Ost[(q + 3) * 72 + cout]);
            *(float4*)&out[rowbase + q] = o;
        }
    }
}

// ---------------------------------------------------------------------------
extern "C" void kernel_launch(void* const* d_in, const int* in_sizes, int n_in,
                              void* d_out, int out_size)
{
    const float* feat = (const float*)d_in[0];
    const float* wa   = (const float*)d_in[1];
    const float* ba   = (const float*)d_in[2];
    const float* wb   = (const float*)d_in[3];
    const float* bb   = (const float*)d_in[4];
    const float* wm   = (const float*)d_in[5];
    const float* bm   = (const float*)d_in[6];
    const float* gam  = (const float*)d_in[7];
    const float* bet  = (const float*)d_in[8];
    const float* mean = (const float*)d_in[9];
    const float* var  = (const float*)d_in[10];
    const float* alph = (const float*)d_in[11];

    const int pre_smem = (12544 + 2 * 128 * 65) * 4;
    cudaFuncSetAttribute(preproc_kernel, cudaFuncAttributeMaxDynamicSharedMemorySize, pre_smem);
    cudaFuncSetAttribute(attn_kernel,    cudaFuncAttributeMaxDynamicSharedMemorySize, SMEM_SZ);

    preproc_kernel<<<dim3(Nn / 128, Bc), 512, pre_smem>>>(
        feat, wa, ba, wb, bb, wm, bm, gam, bet, mean, var);

    attn_kernel<<<dim3(Nn / 128, Bc), 256, SMEM_SZ>>>(
        feat, alph, (float*)d_out);
}

// round 17
// speedup vs baseline: 1.5335x; 1.2082x over previous
#include <cuda_runtime.h>
#include <cuda_fp16.h>
#include <cstdint>

#define Bc 2
#define Cc 64
#define Nn 8192
#define TKc 128
#define NCH (Nn / TKc)    // 64 chunks of 128 keys

// ---------------- device scratch (fp16) ----------------
__device__ __align__(256) __half g_Q [Bc * Nn * Cc];   // [b][n][c] (pre-scaled by log2e)
__device__ __align__(256) __half g_K [Bc * Nn * Cc];   // [b][n][c]
__device__ __align__(256) __half g_V [Bc * Cc * Nn];   // [b][c][n]

// ---------------- helpers ----------------
__device__ __forceinline__ uint32_t smem_u32(const void* p) {
    uint32_t a;
    asm("{ .reg .u64 t; cvta.to.shared.u64 t, %1; cvt.u32.u64 %0, t; }" : "=r"(a) : "l"(p));
    return a;
}
__device__ __forceinline__ void cp16(void* dst, const void* src) {
    unsigned d = smem_u32(dst);
    asm volatile("cp.async.cg.shared.global [%0], [%1], 16;" :: "r"(d), "l"(src));
}
__device__ __forceinline__ void cp_commit() { asm volatile("cp.async.commit_group;" ::: "memory"); }
__device__ __forceinline__ void cp_wait0()  { asm volatile("cp.async.wait_group 0;" ::: "memory"); }
__device__ __forceinline__ void cp_wait1()  { asm volatile("cp.async.wait_group 1;" ::: "memory"); }

__device__ __forceinline__ void ldsm4(uint32_t* r, uint32_t addr) {
    asm volatile("ldmatrix.sync.aligned.m8n8.x4.shared.b16 {%0,%1,%2,%3}, [%4];"
        : "=r"(r[0]), "=r"(r[1]), "=r"(r[2]), "=r"(r[3]) : "r"(addr));
}
__device__ __forceinline__ void mma16816(float* d, const uint32_t* a, const uint32_t* b) {
    asm volatile("mma.sync.aligned.m16n8k16.row.col.f32.f16.f16.f32 "
        "{%0,%1,%2,%3}, {%4,%5,%6,%7}, {%8,%9}, {%0,%1,%2,%3};"
        : "+f"(d[0]), "+f"(d[1]), "+f"(d[2]), "+f"(d[3])
        : "r"(a[0]), "r"(a[1]), "r"(a[2]), "r"(a[3]), "r"(b[0]), "r"(b[1]));
}
__device__ __forceinline__ uint32_t cvtf2(float hi, float lo) {
    uint32_t d;
    asm("cvt.rn.f16x2.f32 %0, %1, %2;" : "=r"(d) : "f"(hi), "f"(lo));
    return d;
}
__device__ __forceinline__ uint32_t ex2h2(uint32_t x) {
    uint32_t d;
    asm("ex2.approx.f16x2 %0, %1;" : "=r"(d) : "r"(x));
    return d;
}
__device__ __forceinline__ float fex2(float x) {
    float y;
    asm("ex2.approx.f32 %0, %1;" : "=f"(y) : "f"(x));
    return y;
}
__device__ __forceinline__ float2 unpackh2(uint32_t p) {
    __half2 h = *reinterpret_cast<__half2*>(&p);
    return __half22float2(h);
}

// XOR-swizzled address within a tile of 128B rows (c16 = 16-byte column 0..7)
__device__ __forceinline__ uint32_t swz(uint32_t row, uint32_t c16) {
    return row * 128 + ((c16 ^ (row & 7)) << 4);
}

// ---------------------------------------------------------------------------
// Preproc: three 64x64 projections + BN fold; emit fp16 Q (log2e-scaled),
// K, V. 512 threads: col = tid&127, o-quarter = tid>>7.
// ---------------------------------------------------------------------------
extern "C" __global__ void __launch_bounds__(512)
preproc_kernel(const float* __restrict__ x,
               const float* __restrict__ wa, const float* __restrict__ ba,
               const float* __restrict__ wb, const float* __restrict__ bb,
               const float* __restrict__ wm, const float* __restrict__ bm,
               const float* __restrict__ gam, const float* __restrict__ bet,
               const float* __restrict__ mean, const float* __restrict__ var)
{
    extern __shared__ float sm[];
    float* swA = sm;             // 4096
    float* swB = sm + 4096;
    float* swM = sm + 8192;
    float* sBa = sm + 12288;
    float* sBb = sBa + 64;
    float* sS  = sBb + 64;
    float* sT  = sS + 64;
    float* sa  = sm + 12544;     // 128*65
    float* sb  = sa + 128 * 65;

    const int tid = threadIdx.x;
    for (int i = tid; i < 4096; i += 512) { swA[i] = wa[i]; swB[i] = wb[i]; swM[i] = wm[i]; }
    if (tid < 64) {
        sBa[tid] = ba[tid];
        sBb[tid] = bb[tid];
        float s = gam[tid] * rsqrtf(var[tid] + 1e-5f);
        sS[tid] = s;
        sT[tid] = (bm[tid] - mean[tid]) * s + bet[tid];
    }
    __syncthreads();

    const int b   = blockIdx.y;
    const int n0  = blockIdx.x * 128;
    const int col = tid & 127;
    const int oq  = tid >> 7;          // o-quarter 0..3
    const int n   = n0 + col;

    float xc[64];
    #pragma unroll
    for (int c = 0; c < 64; c++)
        xc[c] = x[((size_t)b * Cc + c) * Nn + n];

    for (int oo = 0; oo < 16; oo++) {
        const int o = 16 * oq + oo;
        float a0 = 0.f, b0 = 0.f, m0 = 0.f;
        const float4* wA4 = (const float4*)(swA + o * 64);
        const float4* wB4 = (const float4*)(swB + o * 64);
        const float4* wM4 = (const float4*)(swM + o * 64);
        #pragma unroll
        for (int c4 = 0; c4 < 16; c4++) {
            float4 va = wA4[c4], vb = wB4[c4], vm = wM4[c4];
            float x0 = xc[4*c4+0], x1 = xc[4*c4+1], x2 = xc[4*c4+2], x3 = xc[4*c4+3];
            a0 = fmaf(va.x, x0, a0); a0 = fmaf(va.y, x1, a0); a0 = fmaf(va.z, x2, a0); a0 = fmaf(va.w, x3, a0);
            b0 = fmaf(vb.x, x0, b0); b0 = fmaf(vb.y, x1, b0); b0 = fmaf(vb.z, x2, b0); b0 = fmaf(vb.w, x3, b0);
            m0 = fmaf(vm.x, x0, m0); m0 = fmaf(vm.y, x1, m0); m0 = fmaf(vm.z, x2, m0); m0 = fmaf(vm.w, x3, m0);
        }
        sa[col * 65 + o] = (a0 + sBa[o]) * 1.4426950408889634f;   // fold log2e into Q
        sb[col * 65 + o] = b0 + sBb[o];
        float v = fmaf(m0, sS[o], sT[o]);
        g_V[((size_t)b * Cc + o) * Nn + n] = __float2half(v);
    }
    __syncthreads();

    for (int e = tid; e < 128 * 64; e += 512) {
        int r = e >> 6, c = e & 63;
        size_t gi = ((size_t)b * Nn + n0 + r) * 64 + c;
        g_Q[gi] = __float2half(sa[r * 65 + c]);
        g_K[gi] = __float2half(sb[r * 65 + c]);
    }
}

// ---------------------------------------------------------------------------
// Flash attention: CTA = 128 queries, 256 threads (8 warps x 16 q-rows).
// 128-key chunks. QK SINGLE TERM fp16 (Q and K each singly rounded; their
// logit noise substantially cancels in O/l). S preloaded with -mr so the
// softmax needs NO subtraction; range check = local-fmax + warp vote.
// smem: Q 16KB; ring-3 x 32KB chunks (K 16KB | V 2x8KB subtiles).
// ---------------------------------------------------------------------------
#define OFF_Q  0
#define OFF_KV 16384
#define CHUNK_B 32768
#define SMEM_SZ (16384 + 3 * CHUNK_B)      // 112 KB

extern "C" __global__ void __launch_bounds__(256, 1)
attn_kernel(const float* __restrict__ feat, const float* __restrict__ alphap,
            float* __restrict__ out)
{
    extern __shared__ char smc[];
    const uint32_t sb32 = smem_u32(smc);
    const int tid = threadIdx.x;
    const int w   = tid >> 5;
    const int l   = tid & 31;
    const int b   = blockIdx.y;
    const int n0  = blockIdx.x * 128;

    const __half* QG = g_Q + (size_t)b * Nn * Cc;
    const __half* KG = g_K + (size_t)b * Nn * Cc;
    const __half* VG = g_V + (size_t)b * Cc * Nn;

    // ---- issue Q loads (group 0, together with chunk 0): 1024 16B units ----
    #pragma unroll
    for (int i = 0; i < 4; i++) {
        int u = tid + i * 256;
        int row = u >> 3, c16 = u & 7;
        cp16(smc + OFF_Q + swz(row, c16), QG + (size_t)(n0 + row) * 64 + c16 * 8);
    }

    auto load_chunk = [&](int jj) {
        char* base = smc + OFF_KV + (jj % 3) * CHUNK_B;
        int m0 = jj * TKc;
        #pragma unroll
        for (int i = 0; i < 4; i++) {
            int u = tid + i * 256;        // K: 128 rows x 8 c16 = 1024 units
            int row = u >> 3, c16 = u & 7;
            cp16(base + swz(row, c16), KG + (size_t)(m0 + row) * 64 + c16 * 8);
        }
        #pragma unroll
        for (int i = 0; i < 4; i++) {
            int u = tid + i * 256;        // V: 2 subtiles x (64 ch-rows x 8 c16)
            int sub = u >> 9, r = (u >> 3) & 63, c16 = u & 7;
            cp16(base + 16384 + sub * 8192 + swz(r, c16),
                 VG + (size_t)r * Nn + m0 + sub * 64 + c16 * 8);
        }
        cp_commit();
    };

    load_chunk(0);           // group 0: Q + chunk0
    load_chunk(1);           // group 1: chunk1
    cp_wait1();
    __syncthreads();

    // ---- Q fragments (persistent): A of m16n8k16, rows 16w..16w+15 ----
    uint32_t qh[4][4];
    {
        uint32_t qrow = 16 * w + (l & 15);
        #pragma unroll
        for (int s = 0; s < 4; s++)
            ldsm4(qh[s], sb32 + OFF_Q + swz(qrow, 2 * s + (l >> 4)));
    }

    float O[8][4];
    #pragma unroll
    for (int t = 0; t < 8; t++)
        #pragma unroll
        for (int i = 0; i < 4; i++) O[t][i] = 0.f;
    float l0 = 0.f, l1 = 0.f;
    float mr0 = 0.f, mr1 = 0.f;   // softmax reference (running max, log2 units)

    const uint32_t row_b = (l & 7) + ((l >> 4) & 1) * 8;   // B-frag row within 16-tile
    const uint32_t c_b   = (l >> 3) & 1;                   // B-frag 16B-col select

    for (int j = 0; j < NCH; j++) {
        if (j >= NCH - 2) cp_wait0(); else cp_wait1();
        __syncthreads();
        const uint32_t kvb = sb32 + OFF_KV + (uint32_t)(j % 3) * CHUNK_B;

        // prefetch chunk j+2 (buffer consumed at iteration j-1; top barrier guards)
        if (j + 2 < NCH) load_chunk(j + 2);

        // ---- S = Q * K (single term), preloaded with -mr ----
        float S[16][4];
        #pragma unroll
        for (int t = 0; t < 16; t++) {
            S[t][0] = -mr0; S[t][1] = -mr0;
            S[t][2] = -mr1; S[t][3] = -mr1;
        }

        #pragma unroll
        for (int s = 0; s < 4; s++) {
            #pragma unroll
            for (int h = 0; h < 2; h++) {       // K-row halves (4 tiles each)
                uint32_t kf[4][4];
                #pragma unroll
                for (int t = 0; t < 4; t++)
                    ldsm4(kf[t], kvb + swz(16 * (4 * h + t) + row_b, 2 * s + c_b));
                #pragma unroll
                for (int t = 0; t < 4; t++) {
                    mma16816(S[8*h + 2*t],     qh[s], &kf[t][0]);
                    mma16816(S[8*h + 2*t + 1], qh[s], &kf[t][2]);
                }
            }
        }

        // ---- range check: any S > 0 means new row max -> rare update path ----
        {
            float lm = S[0][0];
            #pragma unroll
            for (int t = 0; t < 16; t++)
                lm = fmaxf(lm, fmaxf(fmaxf(S[t][0], S[t][1]), fmaxf(S[t][2], S[t][3])));
            if (__any_sync(0xffffffffu, lm > 0.f)) {
                float m0 = -1e30f, m1 = -1e30f;
                #pragma unroll
                for (int t = 0; t < 16; t++) {
                    m0 = fmaxf(m0, fmaxf(S[t][0], S[t][1]));
                    m1 = fmaxf(m1, fmaxf(S[t][2], S[t][3]));
                }
                m0 = fmaxf(m0, __shfl_xor_sync(0xffffffffu, m0, 1));
                m0 = fmaxf(m0, __shfl_xor_sync(0xffffffffu, m0, 2));
                m1 = fmaxf(m1, __shfl_xor_sync(0xffffffffu, m1, 1));
                m1 = fmaxf(m1, __shfl_xor_sync(0xffffffffu, m1, 2));
                float d0 = fmaxf(m0, 0.f), d1 = fmaxf(m1, 0.f);
                mr0 += d0; mr1 += d1;
                float f0 = fex2(-d0), f1 = fex2(-d1);
                l0 *= f0; l1 *= f1;
                #pragma unroll
                for (int t = 0; t < 8; t++) {
                    O[t][0] *= f0; O[t][1] *= f0;
                    O[t][2] *= f1; O[t][3] *= f1;
                }
                #pragma unroll
                for (int t = 0; t < 16; t++) {
                    S[t][0] -= d0; S[t][1] -= d0;
                    S[t][2] -= d1; S[t][3] -= d1;
                }
            }
        }

        // ---- softmax (pack f16x2, vector ex2; no subtraction) + 1-term PV ----
        #pragma unroll
        for (int sg = 0; sg < 8; sg++) {
            uint32_t ah[4];
            {
                float* c0 = S[2 * sg];
                float* c1 = S[2 * sg + 1];
                uint32_t t0 = cvtf2(c0[1], c0[0]);
                uint32_t t1 = cvtf2(c0[3], c0[2]);
                uint32_t t2 = cvtf2(c1[1], c1[0]);
                uint32_t t3 = cvtf2(c1[3], c1[2]);
                ah[0] = ex2h2(t0);
                ah[1] = ex2h2(t1);
                ah[2] = ex2h2(t2);
                ah[3] = ex2h2(t3);
                // l from the ROUNDED P so O/l shares the rounding error
                float2 a0 = unpackh2(ah[0]), a2 = unpackh2(ah[2]);
                float2 a1 = unpackh2(ah[1]), a3 = unpackh2(ah[3]);
                l0 += a0.x + a0.y + a2.x + a2.y;
                l1 += a1.x + a1.y + a3.x + a3.y;
            }
            const uint32_t vb2 = kvb + 16384 + (uint32_t)(sg >> 2) * 8192;
            const uint32_t sl  = (uint32_t)(sg & 3);
            uint32_t vf[4][4];
            #pragma unroll
            for (int t = 0; t < 4; t++)
                ldsm4(vf[t], vb2 + swz(16 * t + row_b, 2 * sl + c_b));
            #pragma unroll
            for (int t = 0; t < 4; t++) {
                mma16816(O[2*t],   ah, &vf[t][0]);
                mma16816(O[2*t+1], ah, &vf[t][2]);
            }
        }
    }

    // ---- epilogue ----
    l0 += __shfl_xor_sync(0xffffffffu, l0, 1);
    l0 += __shfl_xor_sync(0xffffffffu, l0, 2);
    l1 += __shfl_xor_sync(0xffffffffu, l1, 1);
    l1 += __shfl_xor_sync(0xffffffffu, l1, 2);
    const float ta = 2.f * alphap[0];
    const float s0 = ta / l0, s1 = ta / l1;

    __syncthreads();
    float* Ost = (float*)smc;                  // 128 x 72 staging (36.8 KB)
    {
        int r  = l >> 2, c2 = (l & 3) * 2;
        int q0 = 16 * w + r;
        #pragma unroll
        for (int t = 0; t < 8; t++) {
            int cout = 8 * t + c2;
            *(float2*)&Ost[q0 * 72 + cout]       = make_float2(O[t][0] * s0, O[t][1] * s0);
            *(float2*)&Ost[(q0 + 8) * 72 + cout] = make_float2(O[t][2] * s1, O[t][3] * s1);
        }
    }
    __syncthreads();
    {
        int cout = tid >> 2;
        int qb   = (tid & 3) * 32;
        const size_t rowbase = ((size_t)b * Cc + cout) * Nn + n0;
        #pragma unroll
        for (int i = 0; i < 8; i++) {
            int q = qb + 4 * i;
            float4 f = *(const float4*)&feat[rowbase + q];
            float4 o;
            o.x = fmaf(2.f, f.x, Ost[(q + 0) * 72 + cout]);
            o.y = fmaf(2.f, f.y, Ost[(q + 1) * 72 + cout]);
            o.z = fmaf(2.f, f.z, Ost[(q + 2) * 72 + cout]);
            o.w = fmaf(2.f, f.w, Ost[(q + 3) * 72 + cout]);
            *(float4*)&out[rowbase + q] = o;
        }
    }
}

// ---------------------------------------------------------------------------
extern "C" void kernel_launch(void* const* d_in, const int* in_sizes, int n_in,
                              void* d_out, int out_size)
{
    const float* feat = (const float*)d_in[0];
    const float* wa   = (const float*)d_in[1];
    const float* ba   = (const float*)d_in[2];
    const float* wb   = (const float*)d_in[3];
    const float* bb   = (const float*)d_in[4];
    const float* wm   = (const float*)d_in[5];
    const float* bm   = (const float*)d_in[6];
    const float* gam  = (const float*)d_in[7];
    const float* bet  = (const float*)d_in[8];
    const float* mean = (const float*)d_in[9];
    const float* var  = (const float*)d_in[10];
    const float* alph = (const float*)d_in[11];

    const int pre_smem = (12544 + 2 * 128 * 65) * 4;
    cudaFuncSetAttribute(preproc_kernel, cudaFuncAttributeMaxDynamicSharedMemorySize, pre_smem);
    cudaFuncSetAttribute(attn_kernel,    cudaFuncAttributeMaxDynamicSharedMemorySize, SMEM_SZ);

    preproc_kernel<<<dim3(Nn / 128, Bc), 512, pre_smem>>>(
        feat, wa, ba, wb, bb, wm, bm, gam, bet, mean, var);

    attn_kernel<<<dim3(Nn / 128, Bc), 256, SMEM_SZ>>>(
        feat, alph, (float*)d_out);
}